// round 3
// baseline (speedup 1.0000x reference)
#include <cuda_runtime.h>
#include <float.h>

#define BB 4
#define NR 180
#define CC 512
#define HH 48
#define WW 48
#define F_IN 2048
#define OO 64
#define EPSV 1e-5f
#define C4 (CC/4)        // 128 float4 per (h,w)
#define NSTRIP 8
#define MT 12            // ROIs per gemm tile
#define KSPLIT 4
#define KQ (F_IN/KSPLIT) // 512

// ---------------- device scratch ----------------
__device__ float d_feat_t[BB * HH * WW * CC];     // [B,H,W,C]
__device__ unsigned d_enc[BB * NR * F_IN];        // encoded relu'd pooled maxes
__device__ float d_W1t[F_IN * OO];                // W1 transposed [F,O]
__device__ float d_Wsum[OO];                      // sum_f W1[o,f]
__device__ float d_s1[NR];                        // per-n sum over (b,f)
__device__ float d_s2[NR];                        // per-n sumsq
__device__ float d_g[BB * NR * OO];               // GEMM partial-sum target

__device__ __forceinline__ void max4(float4& a, const float4& b) {
    a.x = fmaxf(a.x, b.x); a.y = fmaxf(a.y, b.y);
    a.z = fmaxf(a.z, b.z); a.w = fmaxf(a.w, b.w);
}
__device__ __forceinline__ unsigned encf(float f) {
    unsigned u = __float_as_uint(f);
    return (u & 0x80000000u) ? ~u : (u | 0x80000000u);
}
__device__ __forceinline__ float decf(unsigned u) {
    // all stored values are >= enc(0), i.e. non-negative floats
    return __uint_as_float(u & 0x7FFFFFFFu);
}

// ---------------- K0: init accumulators ----------------
__global__ void k_zero() {
    int i = blockIdx.x * 256 + threadIdx.x;
    if (i < BB * NR * F_IN) d_enc[i] = 0x80000000u;   // enc(0.0f) -> free ReLU
    if (i < BB * NR * OO) d_g[i] = 0.f;
    if (i < NR) { d_s1[i] = 0.f; d_s2[i] = 0.f; }
}

// ---------------- K1: features [B,C,H,W] -> [B,H,W,C] ----------------
__global__ void k_transpose(const float* __restrict__ feat) {
    __shared__ float tile[32][33];
    int bh = blockIdx.z;
    int b = bh / HH, h = bh % HH;
    int c0 = blockIdx.y * 32;
    int w0 = blockIdx.x * 32;
    #pragma unroll
    for (int k = 0; k < 32; k += 8) {
        int c = c0 + threadIdx.y + k;
        int w = w0 + threadIdx.x;
        if (w < WW)
            tile[threadIdx.y + k][threadIdx.x] = feat[((b * CC + c) * HH + h) * WW + w];
    }
    __syncthreads();
    #pragma unroll
    for (int k = 0; k < 32; k += 8) {
        int w = w0 + threadIdx.y + k;
        int c = c0 + threadIdx.x;
        if (w < WW)
            d_feat_t[(bh * WW + w) * CC + c] = tile[threadIdx.x][threadIdx.y + k];
    }
}

// ---------------- K2: W1 transpose + row sums ----------------
__global__ void k_prep_w1(const float* __restrict__ W1) {
    int o = blockIdx.x;
    float s = 0.f;
    for (int f = threadIdx.x; f < F_IN; f += 256) {
        float v = W1[o * F_IN + f];
        d_W1t[f * OO + o] = v;
        s += v;
    }
    __shared__ float red[256];
    red[threadIdx.x] = s;
    __syncthreads();
    for (int st = 128; st > 0; st >>= 1) {
        if (threadIdx.x < st) red[threadIdx.x] += red[threadIdx.x + st];
        __syncthreads();
    }
    if (threadIdx.x == 0) d_Wsum[o] = red[0];
}

// ---------------- K3: ROI max pool, h-strip blocks, atomicMax merge ----------------
// grid.x = BB*NR, grid.y = NSTRIP; 128 threads = one float4 channel-group each.
__global__ void __launch_bounds__(128) k_roipool(const float* __restrict__ rois) {
    int bn = blockIdx.x;
    int s = blockIdx.y;
    int b = bn / NR;
    const float* r = rois + bn * 4;
    float y1 = r[0] * 0.25f, x1 = r[1] * 0.25f;
    float y2 = r[2] * 0.25f, x2 = r[3] * 0.25f;
    int r0 = (int)truncf(y1), r1 = (int)truncf(x1);
    int r2 = (int)ceilf(y2),  r3 = (int)ceilf(x2);
    if (r0 + s > r2) return;                  // strip has no rows
    int hs = r2 - r0 + 1, ws = r3 - r1 + 1;
    int eh0 = r0 + (hs + 1) / 2;              // rows region0: [r0, eh0)
    int sh1 = r0 + hs / 2;                    // rows region1: [sh1, r2]
    int wA = ws >> 1;                         // cols region0-only
    int wB = ws & 1;                          // overlap col (0 or 1)
    int wC = ws >> 1;                         // cols region1-only

    int cq = threadIdx.x;                     // 0..127

    const float4 NEG = make_float4(-FLT_MAX, -FLT_MAX, -FLT_MAX, -FLT_MAX);
    float4 m00 = NEG, m01 = NEG, m10 = NEG, m11 = NEG;

    const float4* ft = (const float4*)d_feat_t;
    for (int h = r0 + s; h <= r2; h += NSTRIP) {
        const float4* p = ft + ((b * HH + h) * WW + r1) * C4 + cq;
        float4 rm0 = NEG, rm1 = NEG;
        #pragma unroll 2
        for (int w = wA; w > 0; --w) { max4(rm0, *p); p += C4; }
        if (wB) { float4 v = *p; max4(rm0, v); max4(rm1, v); p += C4; }
        #pragma unroll 2
        for (int w = wC; w > 0; --w) { max4(rm1, *p); p += C4; }
        if (h < eh0)  { max4(m00, rm0); max4(m01, rm1); }
        if (h >= sh1) { max4(m10, rm0); max4(m11, rm1); }
    }

    unsigned* out = d_enc + (size_t)bn * F_IN + cq * 16;
    atomicMax(out + 0,  encf(m00.x)); atomicMax(out + 1,  encf(m01.x));
    atomicMax(out + 2,  encf(m10.x)); atomicMax(out + 3,  encf(m11.x));
    atomicMax(out + 4,  encf(m00.y)); atomicMax(out + 5,  encf(m01.y));
    atomicMax(out + 6,  encf(m10.y)); atomicMax(out + 7,  encf(m11.y));
    atomicMax(out + 8,  encf(m00.z)); atomicMax(out + 9,  encf(m01.z));
    atomicMax(out + 10, encf(m10.z)); atomicMax(out + 11, encf(m11.z));
    atomicMax(out + 12, encf(m00.w)); atomicMax(out + 13, encf(m01.w));
    atomicMax(out + 14, encf(m10.w)); atomicMax(out + 15, encf(m11.w));
}

// ---------------- K4: BN1 partial stats from encoded pooled ----------------
__global__ void k_stats(void) {
    int bn = blockIdx.x;              // b*NR+n
    int n = bn % NR;
    const uint4* e = (const uint4*)(d_enc + (size_t)bn * F_IN);
    float s = 0.f, q = 0.f;
    #pragma unroll
    for (int i = 0; i < 2; i++) {
        uint4 u = e[threadIdx.x + i * 256];
        float a = decf(u.x), bb2 = decf(u.y), c = decf(u.z), d = decf(u.w);
        s += a + bb2 + c + d;
        q += a * a + bb2 * bb2 + c * c + d * d;
    }
    __shared__ float rs[256], rq[256];
    rs[threadIdx.x] = s; rq[threadIdx.x] = q;
    __syncthreads();
    for (int st = 128; st > 0; st >>= 1) {
        if (threadIdx.x < st) {
            rs[threadIdx.x] += rs[threadIdx.x + st];
            rq[threadIdx.x] += rq[threadIdx.x + st];
        }
        __syncthreads();
    }
    if (threadIdx.x == 0) {
        atomicAdd(&d_s1[n], rs[0]);
        atomicAdd(&d_s2[n], rq[0]);
    }
}

// ---------------- K5: GEMM, 12-ROI tiles x K/4 split, atomic combine ----------------
__global__ void __launch_bounds__(256) k_gemm() {
    __shared__ float xs[MT][KQ];            // 24KB
    int mb = blockIdx.x;
    int b = mb / (NR / MT);
    int n0 = (mb % (NR / MT)) * MT;
    int k0 = blockIdx.y * KQ;

    int tid = threadIdx.x;
    for (int i = tid; i < MT * KQ; i += 256) {
        int nl = i >> 9, k = i & (KQ - 1);
        xs[nl][k] = decf(d_enc[((size_t)(b * NR + n0 + nl)) * F_IN + k0 + k]);
    }
    __syncthreads();

    int o = tid & 63;
    int g = tid >> 6;
    float a0 = 0.f, a1 = 0.f, a2 = 0.f;
    const float* Wp = d_W1t + k0 * OO + o;
    #pragma unroll 8
    for (int k = 0; k < KQ; k++) {
        float wv = Wp[k * OO];
        a0 = fmaf(xs[3 * g + 0][k], wv, a0);
        a1 = fmaf(xs[3 * g + 1][k], wv, a1);
        a2 = fmaf(xs[3 * g + 2][k], wv, a2);
    }
    atomicAdd(&d_g[((size_t)(b * NR + n0 + 3 * g + 0)) * OO + o], a0);
    atomicAdd(&d_g[((size_t)(b * NR + n0 + 3 * g + 1)) * OO + o], a1);
    atomicAdd(&d_g[((size_t)(b * NR + n0 + 3 * g + 2)) * OO + o], a2);
}

// ---------------- K6: finalize BN1 affine + bias + BN2 + write ----------------
__global__ void k_final(const float* __restrict__ gamma1,
                        const float* __restrict__ beta1,
                        const float* __restrict__ bl1,
                        const float* __restrict__ gamma2,
                        const float* __restrict__ beta2,
                        float* __restrict__ out) {
    int n = blockIdx.x;
    int t = threadIdx.x;
    int b = t >> 6, o = t & 63;

    const float inv1 = 1.0f / (BB * F_IN);
    float mean1 = d_s1[n] * inv1;
    float var1 = d_s2[n] * inv1 - mean1 * mean1;
    float a1 = gamma1[n] * rsqrtf(var1 + EPSV);
    float c1 = beta1[n] - a1 * mean1;

    float y = a1 * d_g[((size_t)(b * NR + n)) * OO + o] + c1 * d_Wsum[o] + bl1[o];

    __shared__ float rs[256], rq[256];
    rs[t] = y;
    rq[t] = y * y;
    __syncthreads();
    for (int st = 128; st > 0; st >>= 1) {
        if (t < st) {
            rs[t] += rs[t + st];
            rq[t] += rq[t + st];
        }
        __syncthreads();
    }
    float mean = rs[0] * (1.0f / 256.0f);
    float var = rq[0] * (1.0f / 256.0f) - mean * mean;
    out[((size_t)(b * NR + n)) * OO + o] =
        (y - mean) * rsqrtf(var + EPSV) * gamma2[n] + beta2[n];
}

// ---------------- launch ----------------
extern "C" void kernel_launch(void* const* d_in, const int* in_sizes, int n_in,
                              void* d_out, int out_size) {
    const float* features = (const float*)d_in[0];
    const float* rois     = (const float*)d_in[1];
    const float* gamma1   = (const float*)d_in[2];
    const float* beta1    = (const float*)d_in[3];
    const float* W1       = (const float*)d_in[4];
    const float* bl1      = (const float*)d_in[5];
    const float* gamma2   = (const float*)d_in[6];
    const float* beta2    = (const float*)d_in[7];
    float* out = (float*)d_out;

    k_zero<<<(BB * NR * F_IN + 255) / 256, 256>>>();
    dim3 tgrid((WW + 31) / 32, (CC + 31) / 32, BB * HH);
    k_transpose<<<tgrid, dim3(32, 8)>>>(features);
    k_prep_w1<<<OO, 256>>>(W1);
    dim3 pgrid(BB * NR, NSTRIP);
    k_roipool<<<pgrid, 128>>>(rois);
    k_stats<<<BB * NR, 256>>>();
    dim3 ggrid(BB * (NR / MT), KSPLIT);
    k_gemm<<<ggrid, 256>>>();
    k_final<<<NR, 256>>>(gamma1, beta1, bl1, gamma2, beta2, out);
}

// round 4
// speedup vs baseline: 1.2965x; 1.2965x over previous
#include <cuda_runtime.h>
#include <float.h>

#define BB 4
#define NR 180
#define CC 512
#define HH 48
#define WW 48
#define HW (HH*WW)
#define F_IN 2048
#define OO 64
#define EPSV 1e-5f
#define C4 (CC/4)        // 128 float4 per (h,w)
#define LVLSZ (BB*HH*WW*CC)
#define MT 12            // ROIs per gemm tile
#define KSPLIT 4
#define KQ (F_IN/KSPLIT) // 512

// ---------------- device scratch ----------------
__device__ float d_feat_t[LVLSZ];               // [B,H,W,C] level-0
__device__ float d_lvl[4 * LVLSZ];              // levels 1..4 of h sparse table
__device__ float d_pooled[BB * NR * F_IN];      // relu'd pooled
__device__ float d_W1t[F_IN * OO];              // W1 transposed [F,O]
__device__ float d_Wsum[OO];                    // sum_f W1[o,f]
__device__ float d_s1[NR];                      // per-n sum over (b,f)
__device__ float d_s2[NR];                      // per-n sumsq
__device__ float d_g[BB * NR * OO];             // GEMM partial-sum target

__device__ __forceinline__ void max4(float4& a, const float4& b) {
    a.x = fmaxf(a.x, b.x); a.y = fmaxf(a.y, b.y);
    a.z = fmaxf(a.z, b.z); a.w = fmaxf(a.w, b.w);
}

// ---------------- K0: zero accumulators ----------------
__global__ void k_zero() {
    int i = blockIdx.x * 256 + threadIdx.x;
    if (i < BB * NR * OO) d_g[i] = 0.f;
    if (i < NR) { d_s1[i] = 0.f; d_s2[i] = 0.f; }
}

// ---------------- K1: features [B,C,H,W] -> [B,(H*W),C] (flat HW) ----------------
__global__ void k_transpose(const float* __restrict__ feat) {
    __shared__ float tile[32][33];
    int b = blockIdx.z;
    int c0 = blockIdx.y * 32;
    int p0 = blockIdx.x * 32;       // flat hw tile (HW=2304 divisible by 32)
    #pragma unroll
    for (int k = 0; k < 32; k += 8) {
        int c = c0 + threadIdx.y + k;
        tile[threadIdx.y + k][threadIdx.x] = feat[((size_t)(b * CC + c)) * HW + p0 + threadIdx.x];
    }
    __syncthreads();
    #pragma unroll
    for (int k = 0; k < 32; k += 8) {
        int p = p0 + threadIdx.y + k;
        d_feat_t[((size_t)b * HW + p) * CC + c0 + threadIdx.x] = tile[threadIdx.x][threadIdx.y + k];
    }
}

// ---------------- K2: sparse-table build over h (levels 1..4) ----------------
// grid: (BB*WW, 4 c-parts), 128 threads; each thread owns one c for one (b,w) column.
__global__ void __launch_bounds__(128) k_build() {
    int bw = blockIdx.x;
    int b = bw / WW, w = bw % WW;
    int c = blockIdx.y * 128 + threadIdx.x;

    size_t base = ((size_t)(b * HH) * WW + w) * CC + c;   // h stride = WW*CC
    const size_t HS = (size_t)WW * CC;

    float v[HH];
    #pragma unroll
    for (int h = 0; h < HH; h++) v[h] = d_feat_t[base + h * HS];

    #pragma unroll
    for (int h = 0; h < HH - 1; h++) v[h] = fmaxf(v[h], v[h + 1]);
    #pragma unroll
    for (int h = 0; h < HH; h++) d_lvl[0 * LVLSZ + base + h * HS] = v[h];

    #pragma unroll
    for (int h = 0; h < HH - 2; h++) v[h] = fmaxf(v[h], v[h + 2]);
    #pragma unroll
    for (int h = 0; h < HH; h++) d_lvl[1 * LVLSZ + base + h * HS] = v[h];

    #pragma unroll
    for (int h = 0; h < HH - 4; h++) v[h] = fmaxf(v[h], v[h + 4]);
    #pragma unroll
    for (int h = 0; h < HH; h++) d_lvl[2 * LVLSZ + base + h * HS] = v[h];

    #pragma unroll
    for (int h = 0; h < HH - 8; h++) v[h] = fmaxf(v[h], v[h + 8]);
    #pragma unroll
    for (int h = 0; h < HH; h++) d_lvl[3 * LVLSZ + base + h * HS] = v[h];
}

// ---------------- K3: W1 transpose + row sums ----------------
__global__ void k_prep_w1(const float* __restrict__ W1) {
    int o = blockIdx.x;
    float s = 0.f;
    for (int f = threadIdx.x; f < F_IN; f += 256) {
        float v = W1[o * F_IN + f];
        d_W1t[f * OO + o] = v;
        s += v;
    }
    __shared__ float red[256];
    red[threadIdx.x] = s;
    __syncthreads();
    for (int st = 128; st > 0; st >>= 1) {
        if (threadIdx.x < st) red[threadIdx.x] += red[threadIdx.x + st];
        __syncthreads();
    }
    if (threadIdx.x == 0) d_Wsum[o] = red[0];
}

// ---------------- K4: ROI pool via 2-lookup range-max + ReLU + BN1 stats ----------
// 256 threads: cq = tid&127 (float4 channel group), half = tid>>7 (w-region).
__global__ void __launch_bounds__(256) k_roipool(const float* __restrict__ rois) {
    int bn = blockIdx.x;
    int b = bn / NR;
    const float* r = rois + bn * 4;
    int r0 = (int)truncf(r[0] * 0.25f), r1 = (int)truncf(r[1] * 0.25f);
    int r2 = (int)ceilf(r[2] * 0.25f),  r3 = (int)ceilf(r[3] * 0.25f);
    int hs = r2 - r0 + 1, ws = r3 - r1 + 1;
    int lenh = (hs + 1) >> 1;                 // both h-regions have this length
    int lenw = (ws + 1) >> 1;                 // both w-regions have this length
    int sh1 = r0 + (hs >> 1);                 // h-region1 start
    int sw1 = r1 + (ws >> 1);                 // w-region1 start

    int k = 31 - __clz(lenh);                 // floor(log2(lenh)), lenh in [1,24]
    int pw = 1 << k;
    const float4* L = (const float4*)((k == 0) ? d_feat_t : (d_lvl + (size_t)(k - 1) * LVLSZ));
    int rowA = r0,  rowA2 = r0 + lenh - pw;   // h-region0 lookups
    int rowB = sh1, rowB2 = sh1 + lenh - pw;  // h-region1 lookups

    int tid = threadIdx.x;
    int cq = tid & 127;
    int half = tid >> 7;
    int wstart = half ? sw1 : r1;

    size_t rb = (size_t)(b * HH) * WW;
    const float4* pA  = L + ((rb + (size_t)rowA  * WW + wstart)) * C4 + cq;
    const float4* pA2 = L + ((rb + (size_t)rowA2 * WW + wstart)) * C4 + cq;
    const float4* pB  = L + ((rb + (size_t)rowB  * WW + wstart)) * C4 + cq;
    const float4* pB2 = L + ((rb + (size_t)rowB2 * WW + wstart)) * C4 + cq;

    const float4 NEG = make_float4(-FLT_MAX, -FLT_MAX, -FLT_MAX, -FLT_MAX);
    float4 m0 = NEG, m1 = NEG;                // (h-region0, h-region1) for this w-half
    #pragma unroll 2
    for (int w = lenw; w > 0; --w) {
        float4 xa = *pA, xa2 = *pA2, xb = *pB, xb2 = *pB2;
        pA += C4; pA2 += C4; pB += C4; pB2 += C4;
        max4(xa, xa2); max4(xb, xb2);
        max4(m0, xa);  max4(m1, xb);
    }

    // merge halves: half0 holds (m00,m10), half1 holds (m01,m11)
    __shared__ float4 sm0[128], sm1[128];
    __shared__ float rs[128], rq[128];
    if (half == 1) { sm0[cq] = m0; sm1[cq] = m1; }
    __syncthreads();
    if (half == 0) {
        const float4 Z = make_float4(0.f, 0.f, 0.f, 0.f);
        float4 m00 = m0, m10 = m1, m01 = sm0[cq], m11 = sm1[cq];
        max4(m00, Z); max4(m01, Z); max4(m10, Z); max4(m11, Z);
        float4 o0 = make_float4(m00.x, m01.x, m10.x, m11.x);
        float4 o1 = make_float4(m00.y, m01.y, m10.y, m11.y);
        float4 o2 = make_float4(m00.z, m01.z, m10.z, m11.z);
        float4 o3 = make_float4(m00.w, m01.w, m10.w, m11.w);
        float4* out = (float4*)(d_pooled + (size_t)bn * F_IN + cq * 16);
        out[0] = o0; out[1] = o1; out[2] = o2; out[3] = o3;
        float s = (o0.x + o0.y + o0.z + o0.w) + (o1.x + o1.y + o1.z + o1.w)
                + (o2.x + o2.y + o2.z + o2.w) + (o3.x + o3.y + o3.z + o3.w);
        float q = o0.x*o0.x + o0.y*o0.y + o0.z*o0.z + o0.w*o0.w
                + o1.x*o1.x + o1.y*o1.y + o1.z*o1.z + o1.w*o1.w
                + o2.x*o2.x + o2.y*o2.y + o2.z*o2.z + o2.w*o2.w
                + o3.x*o3.x + o3.y*o3.y + o3.z*o3.z + o3.w*o3.w;
        rs[cq] = s; rq[cq] = q;
    }
    __syncthreads();
    for (int st = 64; st > 0; st >>= 1) {
        if (tid < st) { rs[tid] += rs[tid + st]; rq[tid] += rq[tid + st]; }
        __syncthreads();
    }
    if (tid == 0) {
        int n = bn % NR;
        atomicAdd(&d_s1[n], rs[0]);
        atomicAdd(&d_s2[n], rq[0]);
    }
}

// ---------------- K5: GEMM, 12-ROI tiles x K/4 split, atomic combine ----------------
__global__ void __launch_bounds__(256) k_gemm() {
    __shared__ float xs[MT][KQ];            // 24KB
    int mb = blockIdx.x;
    int b = mb / (NR / MT);
    int n0 = (mb % (NR / MT)) * MT;
    int k0 = blockIdx.y * KQ;

    int tid = threadIdx.x;
    for (int i = tid; i < MT * KQ; i += 256) {
        int nl = i >> 9, k = i & (KQ - 1);
        xs[nl][k] = d_pooled[((size_t)(b * NR + n0 + nl)) * F_IN + k0 + k];
    }
    __syncthreads();

    int o = tid & 63;
    int g = tid >> 6;
    float a0 = 0.f, a1 = 0.f, a2 = 0.f;
    const float* Wp = d_W1t + k0 * OO + o;
    #pragma unroll 8
    for (int k = 0; k < KQ; k++) {
        float wv = Wp[k * OO];
        a0 = fmaf(xs[3 * g + 0][k], wv, a0);
        a1 = fmaf(xs[3 * g + 1][k], wv, a1);
        a2 = fmaf(xs[3 * g + 2][k], wv, a2);
    }
    atomicAdd(&d_g[((size_t)(b * NR + n0 + 3 * g + 0)) * OO + o], a0);
    atomicAdd(&d_g[((size_t)(b * NR + n0 + 3 * g + 1)) * OO + o], a1);
    atomicAdd(&d_g[((size_t)(b * NR + n0 + 3 * g + 2)) * OO + o], a2);
}

// ---------------- K6: finalize BN1 affine + bias + BN2 + write ----------------
__global__ void k_final(const float* __restrict__ gamma1,
                        const float* __restrict__ beta1,
                        const float* __restrict__ bl1,
                        const float* __restrict__ gamma2,
                        const float* __restrict__ beta2,
                        float* __restrict__ out) {
    int n = blockIdx.x;
    int t = threadIdx.x;
    int b = t >> 6, o = t & 63;

    const float inv1 = 1.0f / (BB * F_IN);
    float mean1 = d_s1[n] * inv1;
    float var1 = d_s2[n] * inv1 - mean1 * mean1;
    float a1 = gamma1[n] * rsqrtf(var1 + EPSV);
    float c1 = beta1[n] - a1 * mean1;

    float y = a1 * d_g[((size_t)(b * NR + n)) * OO + o] + c1 * d_Wsum[o] + bl1[o];

    __shared__ float rs[256], rq[256];
    rs[t] = y;
    rq[t] = y * y;
    __syncthreads();
    for (int st = 128; st > 0; st >>= 1) {
        if (t < st) { rs[t] += rs[t + st]; rq[t] += rq[t + st]; }
        __syncthreads();
    }
    float mean = rs[0] * (1.0f / 256.0f);
    float var = rq[0] * (1.0f / 256.0f) - mean * mean;
    out[((size_t)(b * NR + n)) * OO + o] =
        (y - mean) * rsqrtf(var + EPSV) * gamma2[n] + beta2[n];
}

// ---------------- launch ----------------
extern "C" void kernel_launch(void* const* d_in, const int* in_sizes, int n_in,
                              void* d_out, int out_size) {
    const float* features = (const float*)d_in[0];
    const float* rois     = (const float*)d_in[1];
    const float* gamma1   = (const float*)d_in[2];
    const float* beta1    = (const float*)d_in[3];
    const float* W1       = (const float*)d_in[4];
    const float* bl1      = (const float*)d_in[5];
    const float* gamma2   = (const float*)d_in[6];
    const float* beta2    = (const float*)d_in[7];
    float* out = (float*)d_out;

    k_zero<<<(BB * NR * OO + 255) / 256, 256>>>();
    dim3 tgrid(HW / 32, CC / 32, BB);
    k_transpose<<<tgrid, dim3(32, 8)>>>(features);
    k_prep_w1<<<OO, 256>>>(W1);
    dim3 bgrid(BB * WW, CC / 128);
    k_build<<<bgrid, 128>>>();
    k_roipool<<<BB * NR, 256>>>(rois);
    dim3 ggrid(BB * (NR / MT), KSPLIT);
    k_gemm<<<ggrid, 256>>>();
    k_final<<<NR, 256>>>(gamma1, beta1, bl1, gamma2, beta2, out);
}

// round 5
// speedup vs baseline: 1.3267x; 1.0233x over previous
#include <cuda_runtime.h>
#include <float.h>

#define BB 4
#define NR 180
#define CC 512
#define HH 48
#define WW 48
#define HW (HH*WW)
#define F_IN 2048
#define OO 64
#define EPSV 1e-5f
#define C4 (CC/4)          // 128 float4 per (h,w)
#define LVLSZ (BB*HH*WW*CC)
#define MT 12              // ROIs per gemm block
#define NQ 8               // k-split groups in gemm
#define KQ (F_IN/NQ)       // 256
#define CT 8               // channels per build block
#define SST 2305           // smem stride per channel in build

// ---------------- device scratch ----------------
__device__ float d_feat_t[LVLSZ];               // [B,H,W,C] level-0 (transposed)
__device__ float d_lvl[3 * LVLSZ];              // levels pw=4,8,16
__device__ float d_pooled[BB * NR * F_IN];      // relu'd pooled
__device__ float d_W1t[F_IN * OO];              // W1 transposed [F,O]
__device__ float d_Wsum[OO];                    // sum_f W1[o,f]
__device__ float d_s1[NR];                      // per-n sum over (b,f)
__device__ float d_s2[NR];                      // per-n sumsq
__device__ float d_g[BB * NR * OO];             // GEMM result

__device__ __forceinline__ void max4(float4& a, const float4& b) {
    a.x = fmaxf(a.x, b.x); a.y = fmaxf(a.y, b.y);
    a.z = fmaxf(a.z, b.z); a.w = fmaxf(a.w, b.w);
}

// ---------------- K1: fused transpose + h sparse-table build ----------------
// grid (CC/CT, BB), 384 threads. smem tile ts[CT][HW] (padded stride SST).
__global__ void __launch_bounds__(384) k_build(const float* __restrict__ feat) {
    extern __shared__ float ts[];            // CT*SST floats = 73.76KB
    int c0 = blockIdx.x * CT;
    int b = blockIdx.y;
    int tid = threadIdx.x;

    // --- load: CT*HW floats, contiguous in global ---
    const float4* src = (const float4*)(feat + ((size_t)(b * CC + c0)) * HW);
    #pragma unroll
    for (int j = 0; j < (CT * HW) / (4 * 384); j++) {
        int i4 = tid + j * 384;
        float4 v = src[i4];
        int c = i4 / (HW / 4);
        int p = (i4 % (HW / 4)) * 4;
        float* d = ts + c * SST + p;
        d[0] = v.x; d[1] = v.y; d[2] = v.z; d[3] = v.w;
    }
    __syncthreads();

    // write helper: level L (dst), p items strided by 384
    float* const dsts[4] = { d_feat_t, d_lvl, d_lvl + LVLSZ, d_lvl + 2 * LVLSZ };
    int myc = tid / 48, myw = tid % 48;      // scan column ownership
    float* col = ts + myc * SST + myw;

    #pragma unroll
    for (int lvl = 0; lvl < 4; lvl++) {
        // write current smem content as level `lvl`
        float* dst = dsts[lvl] + (size_t)b * HW * CC + c0;
        #pragma unroll
        for (int j = 0; j < HW / 384; j++) {
            int p = tid + j * 384;
            float4 v0, v1;
            v0.x = ts[0 * SST + p]; v0.y = ts[1 * SST + p];
            v0.z = ts[2 * SST + p]; v0.w = ts[3 * SST + p];
            v1.x = ts[4 * SST + p]; v1.y = ts[5 * SST + p];
            v1.z = ts[6 * SST + p]; v1.w = ts[7 * SST + p];
            float4* dp = (float4*)(dst + (size_t)p * CC);
            dp[0] = v0; dp[1] = v1;
        }
        if (lvl == 3) break;
        __syncthreads();
        // advance scan: lvl0->pw4 needs d=1,2 ; pw4->pw8 d=4 ; pw8->pw16 d=8
        if (lvl == 0) {
            float prev = col[0];
            for (int h = 0; h < HH - 1; h++) {
                float nx = col[(h + 1) * 48];
                col[h * 48] = fmaxf(prev, nx);
                prev = nx;
            }
            prev = col[0];
            for (int h = 0; h < HH - 2; h++) {
                float nx = col[(h + 2) * 48];
                float cur = col[(h + 1) * 48];   // unmodified yet? h+1 modified at iter h+1... read before write order
                // safe form: read col[h] (already final for this pass? no). Use explicit:
                cur = cur; nx = nx;
                col[h * 48] = fmaxf(prev, nx);
                prev = cur;
            }
        } else {
            int d = (lvl == 1) ? 4 : 8;
            for (int h = 0; h < HH - d; h++)
                col[h * 48] = fmaxf(col[h * 48], col[(h + d) * 48]);
        }
        __syncthreads();
    }
}

// ---------------- K2: W1 transpose + row sums + zero BN1 stats ----------------
__global__ void k_prep_w1(const float* __restrict__ W1) {
    if (blockIdx.x == 0 && threadIdx.x < NR) {
        d_s1[threadIdx.x] = 0.f;
        d_s2[threadIdx.x] = 0.f;
    }
    int o = blockIdx.x;
    float s = 0.f;
    for (int f = threadIdx.x; f < F_IN; f += 256) {
        float v = W1[o * F_IN + f];
        d_W1t[f * OO + o] = v;
        s += v;
    }
    __shared__ float red[256];
    red[threadIdx.x] = s;
    __syncthreads();
    for (int st = 128; st > 0; st >>= 1) {
        if (threadIdx.x < st) red[threadIdx.x] += red[threadIdx.x + st];
        __syncthreads();
    }
    if (threadIdx.x == 0) d_Wsum[o] = red[0];
}

// ---------------- K3: ROI pool via range-max lookups + ReLU + BN1 stats --------
__global__ void __launch_bounds__(256) k_roipool(const float* __restrict__ rois) {
    int bn = blockIdx.x;
    int b = bn / NR;
    const float* r = rois + bn * 4;
    int r0 = (int)truncf(r[0] * 0.25f), r1 = (int)truncf(r[1] * 0.25f);
    int r2 = (int)ceilf(r[2] * 0.25f),  r3 = (int)ceilf(r[3] * 0.25f);
    int hs = r2 - r0 + 1, ws = r3 - r1 + 1;
    int lenh = (hs + 1) >> 1;
    int lenw = (ws + 1) >> 1;
    int sh1 = r0 + (hs >> 1);
    int sw1 = r1 + (ws >> 1);

    const float* Lf;
    int pw;
    if (lenh >= 16)     { pw = 16; Lf = d_lvl + 2 * (size_t)LVLSZ; }
    else if (lenh >= 8) { pw = 8;  Lf = d_lvl + (size_t)LVLSZ; }
    else if (lenh >= 4) { pw = 4;  Lf = d_lvl; }
    else                { pw = 1;  Lf = d_feat_t; }
    int nlk = (lenh + pw - 1) / pw;       // 1..3
    const float4* L4 = (const float4*)Lf;

    int tid = threadIdx.x;
    int cq = tid & 127;
    int half = tid >> 7;
    int wstart = half ? sw1 : r1;
    size_t rb = (size_t)(b * HH) * WW;

    const float4 NEG = make_float4(-FLT_MAX, -FLT_MAX, -FLT_MAX, -FLT_MAX);
    float4 m0 = NEG, m1 = NEG;            // (h-region0, h-region1) for this w-half
    int cap = lenh - pw;
    for (int j = 0; j < nlk; j++) {
        int ho = j * pw; if (ho > cap) ho = cap;
        const float4* pA = L4 + (rb + (size_t)(r0  + ho) * WW + wstart) * C4 + cq;
        const float4* pB = L4 + (rb + (size_t)(sh1 + ho) * WW + wstart) * C4 + cq;
        #pragma unroll 2
        for (int w = lenw; w > 0; --w) {
            float4 va = *pA, vb = *pB;
            pA += C4; pB += C4;
            max4(m0, va); max4(m1, vb);
        }
    }

    // merge halves: half0 holds (m00,m10), half1 holds (m01,m11)
    __shared__ float4 sm0[128], sm1[128];
    __shared__ float rs[128], rq[128];
    if (half == 1) { sm0[cq] = m0; sm1[cq] = m1; }
    __syncthreads();
    if (half == 0) {
        const float4 Z = make_float4(0.f, 0.f, 0.f, 0.f);
        float4 m00 = m0, m10 = m1, m01 = sm0[cq], m11 = sm1[cq];
        max4(m00, Z); max4(m01, Z); max4(m10, Z); max4(m11, Z);
        float4 o0 = make_float4(m00.x, m01.x, m10.x, m11.x);
        float4 o1 = make_float4(m00.y, m01.y, m10.y, m11.y);
        float4 o2 = make_float4(m00.z, m01.z, m10.z, m11.z);
        float4 o3 = make_float4(m00.w, m01.w, m10.w, m11.w);
        float4* out = (float4*)(d_pooled + (size_t)bn * F_IN + cq * 16);
        out[0] = o0; out[1] = o1; out[2] = o2; out[3] = o3;
        float s = (o0.x + o0.y + o0.z + o0.w) + (o1.x + o1.y + o1.z + o1.w)
                + (o2.x + o2.y + o2.z + o2.w) + (o3.x + o3.y + o3.z + o3.w);
        float q = o0.x*o0.x + o0.y*o0.y + o0.z*o0.z + o0.w*o0.w
                + o1.x*o1.x + o1.y*o1.y + o1.z*o1.z + o1.w*o1.w
                + o2.x*o2.x + o2.y*o2.y + o2.z*o2.z + o2.w*o2.w
                + o3.x*o3.x + o3.y*o3.y + o3.z*o3.z + o3.w*o3.w;
        rs[cq] = s; rq[cq] = q;
    }
    __syncthreads();
    for (int st = 64; st > 0; st >>= 1) {
        if (tid < st) { rs[tid] += rs[tid + st]; rq[tid] += rq[tid + st]; }
        __syncthreads();
    }
    if (tid == 0) {
        int n = bn % NR;
        atomicAdd(&d_s1[n], rs[0]);
        atomicAdd(&d_s2[n], rq[0]);
    }
}

// ---------------- K4: GEMM, 12 ROIs/block, in-block 8-way k-split ----------------
__global__ void __launch_bounds__(512) k_gemm() {
    extern __shared__ float gsm[];
    float* xs = gsm;                     // [F_IN][MT] k-major, 96KB
    float* part = gsm + F_IN * MT;       // [NQ][MT*OO], 24KB
    int mb = blockIdx.x;
    int b = mb / (NR / MT);
    int n0 = (mb % (NR / MT)) * MT;
    int tid = threadIdx.x;

    // fill xs: 12 ROIs x 2048 f, transposed to k-major
    const float4* P4 = (const float4*)d_pooled;
    #pragma unroll
    for (int j = 0; j < (MT * F_IN) / (4 * 512); j++) {
        int i4 = tid + j * 512;
        int nl = i4 >> 9, k4 = i4 & 511;
        float4 v = P4[((size_t)(b * NR + n0 + nl)) * (F_IN / 4) + k4];
        xs[(k4 * 4 + 0) * MT + nl] = v.x;
        xs[(k4 * 4 + 1) * MT + nl] = v.y;
        xs[(k4 * 4 + 2) * MT + nl] = v.z;
        xs[(k4 * 4 + 3) * MT + nl] = v.w;
    }
    __syncthreads();

    int o = tid & 63;
    int q = tid >> 6;                    // k-group
    float acc[MT];
    #pragma unroll
    for (int i = 0; i < MT; i++) acc[i] = 0.f;
    const float* Wp = d_W1t + (q * KQ) * OO + o;
    const float* xp = xs + (q * KQ) * MT;
    #pragma unroll 4
    for (int k = 0; k < KQ; k++) {
        float wv = Wp[k * OO];
        const float4* xv = (const float4*)(xp + k * MT);
        float4 xa = xv[0], xb = xv[1], xc = xv[2];
        acc[0] = fmaf(xa.x, wv, acc[0]); acc[1]  = fmaf(xa.y, wv, acc[1]);
        acc[2] = fmaf(xa.z, wv, acc[2]); acc[3]  = fmaf(xa.w, wv, acc[3]);
        acc[4] = fmaf(xb.x, wv, acc[4]); acc[5]  = fmaf(xb.y, wv, acc[5]);
        acc[6] = fmaf(xb.z, wv, acc[6]); acc[7]  = fmaf(xb.w, wv, acc[7]);
        acc[8] = fmaf(xc.x, wv, acc[8]); acc[9]  = fmaf(xc.y, wv, acc[9]);
        acc[10] = fmaf(xc.z, wv, acc[10]); acc[11] = fmaf(xc.w, wv, acc[11]);
    }
    #pragma unroll
    for (int nl = 0; nl < MT; nl++)
        part[q * (MT * OO) + nl * OO + o] = acc[nl];
    __syncthreads();

    for (int i = tid; i < MT * OO; i += 512) {
        float g = 0.f;
        #pragma unroll
        for (int qq = 0; qq < NQ; qq++) g += part[qq * (MT * OO) + i];
        int nl = i >> 6, oo = i & 63;
        d_g[((size_t)(b * NR + n0 + nl)) * OO + oo] = g;
    }
}

// ---------------- K5: finalize BN1 affine + bias + BN2 + write ----------------
__global__ void k_final(const float* __restrict__ gamma1,
                        const float* __restrict__ beta1,
                        const float* __restrict__ bl1,
                        const float* __restrict__ gamma2,
                        const float* __restrict__ beta2,
                        float* __restrict__ out) {
    int n = blockIdx.x;
    int t = threadIdx.x;
    int b = t >> 6, o = t & 63;

    const float inv1 = 1.0f / (BB * F_IN);
    float mean1 = d_s1[n] * inv1;
    float var1 = d_s2[n] * inv1 - mean1 * mean1;
    float a1 = gamma1[n] * rsqrtf(var1 + EPSV);
    float c1 = beta1[n] - a1 * mean1;

    float y = a1 * d_g[((size_t)(b * NR + n)) * OO + o] + c1 * d_Wsum[o] + bl1[o];

    __shared__ float rs[256], rq[256];
    rs[t] = y;
    rq[t] = y * y;
    __syncthreads();
    for (int st = 128; st > 0; st >>= 1) {
        if (t < st) { rs[t] += rs[t + st]; rq[t] += rq[t + st]; }
        __syncthreads();
    }
    float mean = rs[0] * (1.0f / 256.0f);
    float var = rq[0] * (1.0f / 256.0f) - mean * mean;
    out[((size_t)(b * NR + n)) * OO + o] =
        (y - mean) * rsqrtf(var + EPSV) * gamma2[n] + beta2[n];
}

// ---------------- launch ----------------
extern "C" void kernel_launch(void* const* d_in, const int* in_sizes, int n_in,
                              void* d_out, int out_size) {
    const float* features = (const float*)d_in[0];
    const float* rois     = (const float*)d_in[1];
    const float* gamma1   = (const float*)d_in[2];
    const float* beta1    = (const float*)d_in[3];
    const float* W1       = (const float*)d_in[4];
    const float* bl1      = (const float*)d_in[5];
    const float* gamma2   = (const float*)d_in[6];
    const float* beta2    = (const float*)d_in[7];
    float* out = (float*)d_out;

    static bool attr_done = false;
    const int BUILD_SMEM = CT * SST * 4;                        // 73760 B
    const int GEMM_SMEM = (F_IN * MT + NQ * MT * OO) * 4;       // 122880 B
    if (!attr_done) {
        cudaFuncSetAttribute(k_build, cudaFuncAttributeMaxDynamicSharedMemorySize, BUILD_SMEM);
        cudaFuncSetAttribute(k_gemm,  cudaFuncAttributeMaxDynamicSharedMemorySize, GEMM_SMEM);
        attr_done = true;
    }

    dim3 bgrid(CC / CT, BB);
    k_build<<<bgrid, 384, BUILD_SMEM>>>(features);
    k_prep_w1<<<OO, 256>>>(W1);
    k_roipool<<<BB * NR, 256>>>(rois);
    k_gemm<<<BB * (NR / MT), 512, GEMM_SMEM>>>();
    k_final<<<NR, 256>>>(gamma1, beta1, bl1, gamma2, beta2, out);
}

// round 6
// speedup vs baseline: 1.5113x; 1.1391x over previous
#include <cuda_runtime.h>
#include <float.h>

#define BB 4
#define NR 180
#define CC 512
#define HH 48
#define WW 48
#define HW (HH*WW)
#define F_IN 2048
#define OO 64
#define EPSV 1e-5f
#define C4 (CC/4)          // 128 float4 per (h,w)
#define LVLSZ (BB*HH*WW*CC)
#define CT 8               // channels per build block
#define SST 2305           // smem stride per channel in build

// ---------------- device scratch ----------------
__device__ float d_feat_t[LVLSZ];               // [B,H,W,C] level-0 (transposed)
__device__ float d_lvl[3 * LVLSZ];              // levels pw=4,8,16
__device__ float d_pooled[BB * NR * F_IN];      // relu'd pooled
__device__ float d_W1t[F_IN * OO];              // W1 transposed [F,O]
__device__ float d_Wsum[OO];                    // sum_f W1[o,f]
__device__ float d_s1[NR];                      // per-n sum over (b,f)
__device__ float d_s2[NR];                      // per-n sumsq
__device__ float d_g2[2][BB * NR * OO];         // GEMM k-half partials

__device__ __forceinline__ void max4(float4& a, const float4& b) {
    a.x = fmaxf(a.x, b.x); a.y = fmaxf(a.y, b.y);
    a.z = fmaxf(a.z, b.z); a.w = fmaxf(a.w, b.w);
}

// ---------------- K1: fused transpose + h sparse-table build ----------------
// grid (CC/CT, BB), 384 threads. smem tile ts[CT][HW] (padded stride SST).
__global__ void __launch_bounds__(384) k_build(const float* __restrict__ feat) {
    extern __shared__ float ts[];            // CT*SST floats = 73.76KB
    int c0 = blockIdx.x * CT;
    int b = blockIdx.y;
    int tid = threadIdx.x;

    // --- load: CT*HW floats, contiguous in global ---
    const float4* src = (const float4*)(feat + ((size_t)(b * CC + c0)) * HW);
    #pragma unroll
    for (int j = 0; j < (CT * HW) / (4 * 384); j++) {
        int i4 = tid + j * 384;
        float4 v = src[i4];
        int c = i4 / (HW / 4);
        int p = (i4 % (HW / 4)) * 4;
        float* d = ts + c * SST + p;
        d[0] = v.x; d[1] = v.y; d[2] = v.z; d[3] = v.w;
    }
    __syncthreads();

    float* const dsts[4] = { d_feat_t, d_lvl, d_lvl + LVLSZ, d_lvl + 2 * LVLSZ };
    int myc = tid / 48, myw = tid % 48;      // scan column ownership
    float* col = ts + myc * SST + myw;

    #pragma unroll
    for (int lvl = 0; lvl < 4; lvl++) {
        // write current smem content as level `lvl` (transposed to [p][C])
        float* dst = dsts[lvl] + (size_t)b * HW * CC + c0;
        #pragma unroll
        for (int j = 0; j < HW / 384; j++) {
            int p = tid + j * 384;
            float4 v0, v1;
            v0.x = ts[0 * SST + p]; v0.y = ts[1 * SST + p];
            v0.z = ts[2 * SST + p]; v0.w = ts[3 * SST + p];
            v1.x = ts[4 * SST + p]; v1.y = ts[5 * SST + p];
            v1.z = ts[6 * SST + p]; v1.w = ts[7 * SST + p];
            float4* dp = (float4*)(dst + (size_t)p * CC);
            dp[0] = v0; dp[1] = v1;
        }
        if (lvl == 3) break;
        __syncthreads();
        if (lvl == 0) {
            // pw1 -> pw4: two in-place passes (d=1 then d=2)
            for (int h = 0; h < HH - 1; h++)
                col[h * 48] = fmaxf(col[h * 48], col[(h + 1) * 48]);
            for (int h = 0; h < HH - 2; h++)
                col[h * 48] = fmaxf(col[h * 48], col[(h + 2) * 48]);
        } else {
            int d = (lvl == 1) ? 4 : 8;
            for (int h = 0; h < HH - d; h++)
                col[h * 48] = fmaxf(col[h * 48], col[(h + d) * 48]);
        }
        __syncthreads();
    }
}

// ---------------- K2: W1 transpose + row sums + zero BN1 stats ----------------
__global__ void k_prep_w1(const float* __restrict__ W1) {
    if (blockIdx.x == 0 && threadIdx.x < NR) {
        d_s1[threadIdx.x] = 0.f;
        d_s2[threadIdx.x] = 0.f;
    }
    int o = blockIdx.x;
    float s = 0.f;
    for (int f = threadIdx.x; f < F_IN; f += 256) {
        float v = W1[o * F_IN + f];
        d_W1t[f * OO + o] = v;
        s += v;
    }
    __shared__ float red[256];
    red[threadIdx.x] = s;
    __syncthreads();
    for (int st = 128; st > 0; st >>= 1) {
        if (threadIdx.x < st) red[threadIdx.x] += red[threadIdx.x + st];
        __syncthreads();
    }
    if (threadIdx.x == 0) d_Wsum[o] = red[0];
}

// ---------------- K3: ROI pool via range-max lookups + ReLU + BN1 stats --------
__global__ void __launch_bounds__(256) k_roipool(const float* __restrict__ rois) {
    int bn = blockIdx.x;
    int b = bn / NR;
    const float* r = rois + bn * 4;
    int r0 = (int)truncf(r[0] * 0.25f), r1 = (int)truncf(r[1] * 0.25f);
    int r2 = (int)ceilf(r[2] * 0.25f),  r3 = (int)ceilf(r[3] * 0.25f);
    int hs = r2 - r0 + 1, ws = r3 - r1 + 1;
    int lenh = (hs + 1) >> 1;
    int lenw = (ws + 1) >> 1;
    int sh1 = r0 + (hs >> 1);
    int sw1 = r1 + (ws >> 1);

    const float* Lf;
    int pw;
    if (lenh >= 16)     { pw = 16; Lf = d_lvl + 2 * (size_t)LVLSZ; }
    else if (lenh >= 8) { pw = 8;  Lf = d_lvl + (size_t)LVLSZ; }
    else if (lenh >= 4) { pw = 4;  Lf = d_lvl; }
    else                { pw = 1;  Lf = d_feat_t; }
    int nlk = (lenh + pw - 1) / pw;       // 1..3
    const float4* L4 = (const float4*)Lf;

    int tid = threadIdx.x;
    int cq = tid & 127;
    int half = tid >> 7;
    int wstart = half ? sw1 : r1;
    size_t rb = (size_t)(b * HH) * WW;

    const float4 NEG = make_float4(-FLT_MAX, -FLT_MAX, -FLT_MAX, -FLT_MAX);
    float4 m0 = NEG, m1 = NEG;            // (h-region0, h-region1) for this w-half
    int cap = lenh - pw;
    for (int j = 0; j < nlk; j++) {
        int ho = j * pw; if (ho > cap) ho = cap;
        const float4* pA = L4 + (rb + (size_t)(r0  + ho) * WW + wstart) * C4 + cq;
        const float4* pB = L4 + (rb + (size_t)(sh1 + ho) * WW + wstart) * C4 + cq;
        #pragma unroll 2
        for (int w = lenw; w > 0; --w) {
            float4 va = *pA, vb = *pB;
            pA += C4; pB += C4;
            max4(m0, va); max4(m1, vb);
        }
    }

    // merge halves: half0 holds (m00,m10), half1 holds (m01,m11)
    __shared__ float4 sm0[128], sm1[128];
    __shared__ float rs[128], rq[128];
    if (half == 1) { sm0[cq] = m0; sm1[cq] = m1; }
    __syncthreads();
    if (half == 0) {
        const float4 Z = make_float4(0.f, 0.f, 0.f, 0.f);
        float4 m00 = m0, m10 = m1, m01 = sm0[cq], m11 = sm1[cq];
        max4(m00, Z); max4(m01, Z); max4(m10, Z); max4(m11, Z);
        float4 o0 = make_float4(m00.x, m01.x, m10.x, m11.x);
        float4 o1 = make_float4(m00.y, m01.y, m10.y, m11.y);
        float4 o2 = make_float4(m00.z, m01.z, m10.z, m11.z);
        float4 o3 = make_float4(m00.w, m01.w, m10.w, m11.w);
        float4* out = (float4*)(d_pooled + (size_t)bn * F_IN + cq * 16);
        out[0] = o0; out[1] = o1; out[2] = o2; out[3] = o3;
        float s = (o0.x + o0.y + o0.z + o0.w) + (o1.x + o1.y + o1.z + o1.w)
                + (o2.x + o2.y + o2.z + o2.w) + (o3.x + o3.y + o3.z + o3.w);
        float q = o0.x*o0.x + o0.y*o0.y + o0.z*o0.z + o0.w*o0.w
                + o1.x*o1.x + o1.y*o1.y + o1.z*o1.z + o1.w*o1.w
                + o2.x*o2.x + o2.y*o2.y + o2.z*o2.z + o2.w*o2.w
                + o3.x*o3.x + o3.y*o3.y + o3.z*o3.z + o3.w*o3.w;
        rs[cq] = s; rq[cq] = q;
    }
    __syncthreads();
    for (int st = 64; st > 0; st >>= 1) {
        if (tid < st) { rs[tid] += rs[tid + st]; rq[tid] += rq[tid + st]; }
        __syncthreads();
    }
    if (tid == 0) {
        int n = bn % NR;
        atomicAdd(&d_s1[n], rs[0]);
        atomicAdd(&d_s2[n], rq[0]);
    }
}

// ---------------- K4: GEMM v3 — 4 ROIs x 2 k-halves, 360 blocks ----------------
// 256 threads = 32 o-pairs x 8 k-groups(128k). No atomics; halves land in d_g2.
__global__ void __launch_bounds__(256) k_gemm() {
    __shared__ float xs[4][1024];            // 16KB, row-major
    __shared__ float part[8][4][OO];         // 8KB
    int mb = blockIdx.x;                     // 0..179
    int kh = blockIdx.y;                     // 0..1
    int b = mb / (NR / 4);
    int n0 = (mb % (NR / 4)) * 4;
    int tid = threadIdx.x;

    const float4* P4 = (const float4*)d_pooled;
    #pragma unroll
    for (int j = 0; j < 4; j++) {
        int i4 = tid + j * 256;              // 0..1023
        int nl = i4 >> 8, k4 = i4 & 255;
        float4 v = P4[((size_t)(b * NR + n0 + nl)) * (F_IN / 4) + kh * 256 + k4];
        *(float4*)&xs[nl][k4 * 4] = v;
    }
    __syncthreads();

    int o2 = (tid & 31) * 2;                 // even o; thread owns (o2, o2+1)
    int q = tid >> 5;                        // 0..7, k-group of 128
    float acc[4][2] = {};
    const float* Wp = d_W1t + (size_t)(kh * 1024 + q * 128) * OO;
    #pragma unroll 2
    for (int k = 0; k < 128; k += 4) {
        float2 w0 = *(const float2*)&Wp[(k + 0) * OO + o2];
        float2 w1 = *(const float2*)&Wp[(k + 1) * OO + o2];
        float2 w2 = *(const float2*)&Wp[(k + 2) * OO + o2];
        float2 w3 = *(const float2*)&Wp[(k + 3) * OO + o2];
        #pragma unroll
        for (int nl = 0; nl < 4; nl++) {
            float4 x = *(const float4*)&xs[nl][q * 128 + k];
            acc[nl][0] = fmaf(x.x, w0.x, acc[nl][0]);
            acc[nl][1] = fmaf(x.x, w0.y, acc[nl][1]);
            acc[nl][0] = fmaf(x.y, w1.x, acc[nl][0]);
            acc[nl][1] = fmaf(x.y, w1.y, acc[nl][1]);
            acc[nl][0] = fmaf(x.z, w2.x, acc[nl][0]);
            acc[nl][1] = fmaf(x.z, w2.y, acc[nl][1]);
            acc[nl][0] = fmaf(x.w, w3.x, acc[nl][0]);
            acc[nl][1] = fmaf(x.w, w3.y, acc[nl][1]);
        }
    }
    #pragma unroll
    for (int nl = 0; nl < 4; nl++) {
        part[q][nl][o2] = acc[nl][0];
        part[q][nl][o2 + 1] = acc[nl][1];
    }
    __syncthreads();

    int nl = tid >> 6, o = tid & 63;
    float g = 0.f;
    #pragma unroll
    for (int qq = 0; qq < 8; qq++) g += part[qq][nl][o];
    d_g2[kh][((size_t)(b * NR + n0 + nl)) * OO + o] = g;
}

// ---------------- K5: finalize BN1 affine + bias + BN2 + write ----------------
__global__ void k_final(const float* __restrict__ gamma1,
                        const float* __restrict__ beta1,
                        const float* __restrict__ bl1,
                        const float* __restrict__ gamma2,
                        const float* __restrict__ beta2,
                        float* __restrict__ out) {
    int n = blockIdx.x;
    int t = threadIdx.x;
    int b = t >> 6, o = t & 63;

    const float inv1 = 1.0f / (BB * F_IN);
    float mean1 = d_s1[n] * inv1;
    float var1 = d_s2[n] * inv1 - mean1 * mean1;
    float a1 = gamma1[n] * rsqrtf(var1 + EPSV);
    float c1 = beta1[n] - a1 * mean1;

    size_t gi = ((size_t)(b * NR + n)) * OO + o;
    float y = a1 * (d_g2[0][gi] + d_g2[1][gi]) + c1 * d_Wsum[o] + bl1[o];

    __shared__ float rs[256], rq[256];
    rs[t] = y;
    rq[t] = y * y;
    __syncthreads();
    for (int st = 128; st > 0; st >>= 1) {
        if (t < st) { rs[t] += rs[t + st]; rq[t] += rq[t + st]; }
        __syncthreads();
    }
    float mean = rs[0] * (1.0f / 256.0f);
    float var = rq[0] * (1.0f / 256.0f) - mean * mean;
    out[gi] = (y - mean) * rsqrtf(var + EPSV) * gamma2[n] + beta2[n];
}

// ---------------- launch ----------------
extern "C" void kernel_launch(void* const* d_in, const int* in_sizes, int n_in,
                              void* d_out, int out_size) {
    const float* features = (const float*)d_in[0];
    const float* rois     = (const float*)d_in[1];
    const float* gamma1   = (const float*)d_in[2];
    const float* beta1    = (const float*)d_in[3];
    const float* W1       = (const float*)d_in[4];
    const float* bl1      = (const float*)d_in[5];
    const float* gamma2   = (const float*)d_in[6];
    const float* beta2    = (const float*)d_in[7];
    float* out = (float*)d_out;

    static bool attr_done = false;
    const int BUILD_SMEM = CT * SST * 4;     // 73760 B
    if (!attr_done) {
        cudaFuncSetAttribute(k_build, cudaFuncAttributeMaxDynamicSharedMemorySize, BUILD_SMEM);
        attr_done = true;
    }

    dim3 bgrid(CC / CT, BB);
    k_build<<<bgrid, 384, BUILD_SMEM>>>(features);
    k_prep_w1<<<OO, 256>>>(W1);
    k_roipool<<<BB * NR, 256>>>(rois);
    dim3 ggrid(BB * (NR / 4), 2);
    k_gemm<<<ggrid, 256>>>();
    k_final<<<NR, 256>>>(gamma1, beta1, bl1, gamma2, beta2, out);
}

// round 7
// speedup vs baseline: 1.5478x; 1.0242x over previous
#include <cuda_runtime.h>
#include <float.h>

#define BB 4
#define NR 180
#define CC 512
#define HH 48
#define WW 48
#define HW (HH*WW)
#define F_IN 2048
#define OO 64
#define EPSV 1e-5f
#define C4 (CC/4)          // 128 float4 per (h,w)
#define LVLSZ (BB*HH*WW*CC)
#define CT 8               // channels per build block
#define SST 2305           // smem stride per channel in build
#define KS 8               // gemm k-split
#define KQ (F_IN/KS)       // 256

// ---------------- device scratch ----------------
__device__ float d_feat_t[LVLSZ];               // [B,H,W,C] level-0 (transposed)
__device__ float d_lvl[3 * LVLSZ];              // levels pw=4,8,16
__device__ float d_pooled[BB * NR * F_IN];      // relu'd pooled
__device__ float d_W1t[F_IN * OO];              // W1 transposed [F,O]
__device__ float d_Wsum[OO];                    // sum_f W1[o,f]
__device__ float d_s1[NR];                      // per-n sum over (b,f)
__device__ float d_s2[NR];                      // per-n sumsq
__device__ float d_g8[KS][BB * NR * OO];        // GEMM k-slice partials

__device__ __forceinline__ void max4(float4& a, const float4& b) {
    a.x = fmaxf(a.x, b.x); a.y = fmaxf(a.y, b.y);
    a.z = fmaxf(a.z, b.z); a.w = fmaxf(a.w, b.w);
}

// ---------------- K1: fused transpose + h sparse-table build ----------------
__global__ void __launch_bounds__(384) k_build(const float* __restrict__ feat) {
    extern __shared__ float ts[];            // CT*SST floats = 73.76KB
    int c0 = blockIdx.x * CT;
    int b = blockIdx.y;
    int tid = threadIdx.x;

    const float4* src = (const float4*)(feat + ((size_t)(b * CC + c0)) * HW);
    #pragma unroll
    for (int j = 0; j < (CT * HW) / (4 * 384); j++) {
        int i4 = tid + j * 384;
        float4 v = src[i4];
        int c = i4 / (HW / 4);
        int p = (i4 % (HW / 4)) * 4;
        float* d = ts + c * SST + p;
        d[0] = v.x; d[1] = v.y; d[2] = v.z; d[3] = v.w;
    }
    __syncthreads();

    float* const dsts[4] = { d_feat_t, d_lvl, d_lvl + LVLSZ, d_lvl + 2 * LVLSZ };
    int myc = tid / 48, myw = tid % 48;
    float* col = ts + myc * SST + myw;

    #pragma unroll
    for (int lvl = 0; lvl < 4; lvl++) {
        float* dst = dsts[lvl] + (size_t)b * HW * CC + c0;
        #pragma unroll
        for (int j = 0; j < HW / 384; j++) {
            int p = tid + j * 384;
            float4 v0, v1;
            v0.x = ts[0 * SST + p]; v0.y = ts[1 * SST + p];
            v0.z = ts[2 * SST + p]; v0.w = ts[3 * SST + p];
            v1.x = ts[4 * SST + p]; v1.y = ts[5 * SST + p];
            v1.z = ts[6 * SST + p]; v1.w = ts[7 * SST + p];
            float4* dp = (float4*)(dst + (size_t)p * CC);
            dp[0] = v0; dp[1] = v1;
        }
        if (lvl == 3) break;
        __syncthreads();
        if (lvl == 0) {
            for (int h = 0; h < HH - 1; h++)
                col[h * 48] = fmaxf(col[h * 48], col[(h + 1) * 48]);
            for (int h = 0; h < HH - 2; h++)
                col[h * 48] = fmaxf(col[h * 48], col[(h + 2) * 48]);
        } else {
            int d = (lvl == 1) ? 4 : 8;
            for (int h = 0; h < HH - d; h++)
                col[h * 48] = fmaxf(col[h * 48], col[(h + d) * 48]);
        }
        __syncthreads();
    }
}

// ---------------- K2: W1 transpose + row sums + zero BN1 stats ----------------
__global__ void k_prep_w1(const float* __restrict__ W1) {
    if (blockIdx.x == 0 && threadIdx.x < NR) {
        d_s1[threadIdx.x] = 0.f;
        d_s2[threadIdx.x] = 0.f;
    }
    int o = blockIdx.x;
    float s = 0.f;
    for (int f = threadIdx.x; f < F_IN; f += 256) {
        float v = W1[o * F_IN + f];
        d_W1t[f * OO + o] = v;
        s += v;
    }
    __shared__ float red[256];
    red[threadIdx.x] = s;
    __syncthreads();
    for (int st = 128; st > 0; st >>= 1) {
        if (threadIdx.x < st) red[threadIdx.x] += red[threadIdx.x + st];
        __syncthreads();
    }
    if (threadIdx.x == 0) d_Wsum[o] = red[0];
}

// ---------------- K3: ROI pool via range-max lookups + ReLU + BN1 stats --------
__global__ void __launch_bounds__(256) k_roipool(const float* __restrict__ rois) {
    int bn = blockIdx.x;
    int b = bn / NR;
    const float* r = rois + bn * 4;
    int r0 = (int)truncf(r[0] * 0.25f), r1 = (int)truncf(r[1] * 0.25f);
    int r2 = (int)ceilf(r[2] * 0.25f),  r3 = (int)ceilf(r[3] * 0.25f);
    int hs = r2 - r0 + 1, ws = r3 - r1 + 1;
    int lenh = (hs + 1) >> 1;
    int lenw = (ws + 1) >> 1;
    int sh1 = r0 + (hs >> 1);
    int sw1 = r1 + (ws >> 1);

    const float* Lf;
    int pw;
    if (lenh >= 16)     { pw = 16; Lf = d_lvl + 2 * (size_t)LVLSZ; }
    else if (lenh >= 8) { pw = 8;  Lf = d_lvl + (size_t)LVLSZ; }
    else if (lenh >= 4) { pw = 4;  Lf = d_lvl; }
    else                { pw = 1;  Lf = d_feat_t; }
    int nlk = (lenh + pw - 1) / pw;       // 1..3
    const float4* L4 = (const float4*)Lf;

    int tid = threadIdx.x;
    int cq = tid & 127;
    int half = tid >> 7;
    int wstart = half ? sw1 : r1;
    size_t rb = (size_t)(b * HH) * WW;

    const float4 NEG = make_float4(-FLT_MAX, -FLT_MAX, -FLT_MAX, -FLT_MAX);
    float4 m0 = NEG, m1 = NEG;
    int cap = lenh - pw;
    for (int j = 0; j < nlk; j++) {
        int ho = j * pw; if (ho > cap) ho = cap;
        const float4* pA = L4 + (rb + (size_t)(r0  + ho) * WW + wstart) * C4 + cq;
        const float4* pB = L4 + (rb + (size_t)(sh1 + ho) * WW + wstart) * C4 + cq;
        #pragma unroll 2
        for (int w = lenw; w > 0; --w) {
            float4 va = *pA, vb = *pB;
            pA += C4; pB += C4;
            max4(m0, va); max4(m1, vb);
        }
    }

    __shared__ float4 sm0[128], sm1[128];
    __shared__ float rs[128], rq[128];
    if (half == 1) { sm0[cq] = m0; sm1[cq] = m1; }
    __syncthreads();
    if (half == 0) {
        const float4 Z = make_float4(0.f, 0.f, 0.f, 0.f);
        float4 m00 = m0, m10 = m1, m01 = sm0[cq], m11 = sm1[cq];
        max4(m00, Z); max4(m01, Z); max4(m10, Z); max4(m11, Z);
        float4 o0 = make_float4(m00.x, m01.x, m10.x, m11.x);
        float4 o1 = make_float4(m00.y, m01.y, m10.y, m11.y);
        float4 o2 = make_float4(m00.z, m01.z, m10.z, m11.z);
        float4 o3 = make_float4(m00.w, m01.w, m10.w, m11.w);
        float4* out = (float4*)(d_pooled + (size_t)bn * F_IN + cq * 16);
        out[0] = o0; out[1] = o1; out[2] = o2; out[3] = o3;
        float s = (o0.x + o0.y + o0.z + o0.w) + (o1.x + o1.y + o1.z + o1.w)
                + (o2.x + o2.y + o2.z + o2.w) + (o3.x + o3.y + o3.z + o3.w);
        float q = o0.x*o0.x + o0.y*o0.y + o0.z*o0.z + o0.w*o0.w
                + o1.x*o1.x + o1.y*o1.y + o1.z*o1.z + o1.w*o1.w
                + o2.x*o2.x + o2.y*o2.y + o2.z*o2.z + o2.w*o2.w
                + o3.x*o3.x + o3.y*o3.y + o3.z*o3.z + o3.w*o3.w;
        rs[cq] = s; rq[cq] = q;
    }
    __syncthreads();
    for (int st = 64; st > 0; st >>= 1) {
        if (tid < st) { rs[tid] += rs[tid + st]; rq[tid] += rq[tid + st]; }
        __syncthreads();
    }
    if (tid == 0) {
        int n = bn % NR;
        atomicAdd(&d_s1[n], rs[0]);
        atomicAdd(&d_s2[n], rq[0]);
    }
}

// ---------------- K4: GEMM v4 — 4 ROIs x 8 k-slices, 1440 blocks ----------------
// 256 threads = 32 o-pairs x 8 q-groups(32k each). No atomics.
__global__ void __launch_bounds__(256) k_gemm() {
    __shared__ float xs[4][KQ];              // 4KB
    __shared__ float part[8][4][OO];         // 8KB
    int mb = blockIdx.x;                     // 0..179
    int ks = blockIdx.y;                     // 0..7
    int b = mb / (NR / 4);
    int n0 = (mb % (NR / 4)) * 4;
    int tid = threadIdx.x;

    // load xs: 4 ROIs x 256 k = 256 float4, one per thread
    {
        int nl = tid >> 6, k4 = tid & 63;
        const float4* P4 = (const float4*)d_pooled;
        float4 v = P4[((size_t)(b * NR + n0 + nl)) * (F_IN / 4) + ks * (KQ / 4) + k4];
        *(float4*)&xs[nl][k4 * 4] = v;
    }
    __syncthreads();

    int o2 = (tid & 31) * 2;
    int q = tid >> 5;                        // 0..7, covers 32 k
    float acc[4][2] = {};
    const float* Wp = d_W1t + (size_t)(ks * KQ + q * 32) * OO;
    #pragma unroll 2
    for (int k = 0; k < 32; k += 4) {
        float2 w0 = *(const float2*)&Wp[(k + 0) * OO + o2];
        float2 w1 = *(const float2*)&Wp[(k + 1) * OO + o2];
        float2 w2 = *(const float2*)&Wp[(k + 2) * OO + o2];
        float2 w3 = *(const float2*)&Wp[(k + 3) * OO + o2];
        #pragma unroll
        for (int nl = 0; nl < 4; nl++) {
            float4 x = *(const float4*)&xs[nl][q * 32 + k];
            acc[nl][0] = fmaf(x.x, w0.x, acc[nl][0]);
            acc[nl][1] = fmaf(x.x, w0.y, acc[nl][1]);
            acc[nl][0] = fmaf(x.y, w1.x, acc[nl][0]);
            acc[nl][1] = fmaf(x.y, w1.y, acc[nl][1]);
            acc[nl][0] = fmaf(x.z, w2.x, acc[nl][0]);
            acc[nl][1] = fmaf(x.z, w2.y, acc[nl][1]);
            acc[nl][0] = fmaf(x.w, w3.x, acc[nl][0]);
            acc[nl][1] = fmaf(x.w, w3.y, acc[nl][1]);
        }
    }
    #pragma unroll
    for (int nl = 0; nl < 4; nl++) {
        part[q][nl][o2] = acc[nl][0];
        part[q][nl][o2 + 1] = acc[nl][1];
    }
    __syncthreads();

    int nl = tid >> 6, o = tid & 63;
    float g = 0.f;
    #pragma unroll
    for (int qq = 0; qq < 8; qq++) g += part[qq][nl][o];
    d_g8[ks][((size_t)(b * NR + n0 + nl)) * OO + o] = g;
}

// ---------------- K5: finalize BN1 affine + bias + BN2 + write ----------------
__global__ void k_final(const float* __restrict__ gamma1,
                        const float* __restrict__ beta1,
                        const float* __restrict__ bl1,
                        const float* __restrict__ gamma2,
                        const float* __restrict__ beta2,
                        float* __restrict__ out) {
    int n = blockIdx.x;
    int t = threadIdx.x;
    int b = t >> 6, o = t & 63;

    const float inv1 = 1.0f / (BB * F_IN);
    float mean1 = d_s1[n] * inv1;
    float var1 = d_s2[n] * inv1 - mean1 * mean1;
    float a1 = gamma1[n] * rsqrtf(var1 + EPSV);
    float c1 = beta1[n] - a1 * mean1;

    size_t gi = ((size_t)(b * NR + n)) * OO + o;
    float gsum = 0.f;
    #pragma unroll
    for (int ks = 0; ks < KS; ks++) gsum += d_g8[ks][gi];
    float y = a1 * gsum + c1 * d_Wsum[o] + bl1[o];

    __shared__ float rs[256], rq[256];
    rs[t] = y;
    rq[t] = y * y;
    __syncthreads();
    for (int st = 128; st > 0; st >>= 1) {
        if (t < st) { rs[t] += rs[t + st]; rq[t] += rq[t + st]; }
        __syncthreads();
    }
    float mean = rs[0] * (1.0f / 256.0f);
    float var = rq[0] * (1.0f / 256.0f) - mean * mean;
    out[gi] = (y - mean) * rsqrtf(var + EPSV) * gamma2[n] + beta2[n];
}

// ---------------- launch ----------------
extern "C" void kernel_launch(void* const* d_in, const int* in_sizes, int n_in,
                              void* d_out, int out_size) {
    const float* features = (const float*)d_in[0];
    const float* rois     = (const float*)d_in[1];
    const float* gamma1   = (const float*)d_in[2];
    const float* beta1    = (const float*)d_in[3];
    const float* W1       = (const float*)d_in[4];
    const float* bl1      = (const float*)d_in[5];
    const float* gamma2   = (const float*)d_in[6];
    const float* beta2    = (const float*)d_in[7];
    float* out = (float*)d_out;

    static bool attr_done = false;
    const int BUILD_SMEM = CT * SST * 4;     // 73760 B
    if (!attr_done) {
        cudaFuncSetAttribute(k_build, cudaFuncAttributeMaxDynamicSharedMemorySize, BUILD_SMEM);
        attr_done = true;
    }

    dim3 bgrid(CC / CT, BB);
    k_build<<<bgrid, 384, BUILD_SMEM>>>(features);
    k_prep_w1<<<OO, 256>>>(W1);
    k_roipool<<<BB * NR, 256>>>(rois);
    dim3 ggrid(BB * (NR / 4), KS);
    k_gemm<<<ggrid, 256>>>();
    k_final<<<NR, 256>>>(gamma1, beta1, bl1, gamma2, beta2, out);
}

// round 9
// speedup vs baseline: 1.8699x; 1.2081x over previous
#include <cuda_runtime.h>
#include <float.h>

#define BB 4
#define NR 180
#define CC 512
#define HH 48
#define WW 48
#define HW (HH*WW)
#define F_IN 2048
#define OO 64
#define EPSV 1e-5f
#define C4 (CC/4)          // 128 float4 per (h,w)
#define LVLSZ (BB*HH*WW*CC)
#define CT 8               // channels per build block
#define SST 2305           // smem stride per channel in build
#define MT 12              // ROIs per gemm block (180/12 = 15)
#define KS 16              // gemm k-split
#define KQ (F_IN/KS)       // 128

// ---------------- device scratch ----------------
__device__ float d_feat_t[LVLSZ];               // [B,H,W,C] level-0 (transposed)
__device__ float d_lvl[2 * LVLSZ];              // levels pw=4, pw=12
__device__ float d_pooled[BB * NR * F_IN];      // relu'd pooled
__device__ float d_W1t[F_IN * OO];              // W1 transposed [F,O]
__device__ float d_Wsum[OO];                    // sum_f W1[o,f]
__device__ float d_s1[NR];                      // per-n sum over (b,f)
__device__ float d_s2[NR];                      // per-n sumsq
__device__ float d_g16[KS][BB * NR * OO];       // GEMM k-slice partials

__device__ __forceinline__ void max4(float4& a, const float4& b) {
    a.x = fmaxf(a.x, b.x); a.y = fmaxf(a.y, b.y);
    a.z = fmaxf(a.z, b.z); a.w = fmaxf(a.w, b.w);
}

// ---------------- K1: fused transpose + sparse-table build + W1 prep ----------
// blocks 0..255: build (c0, b). blocks 256..319: W1 transpose/rowsum.
__global__ void __launch_bounds__(384) k_build(const float* __restrict__ feat,
                                               const float* __restrict__ W1) {
    int blk = blockIdx.x;
    int tid = threadIdx.x;

    if (blk >= (CC / CT) * BB) {
        // ---- W1 prep path ----
        int o = blk - (CC / CT) * BB;           // 0..63
        if (o == 0 && tid < NR) { d_s1[tid] = 0.f; d_s2[tid] = 0.f; }
        __shared__ float red[384];
        float s = 0.f;
        for (int f = tid; f < F_IN; f += 384) {
            float v = W1[o * F_IN + f];
            d_W1t[f * OO + o] = v;
            s += v;
        }
        red[tid] = s;
        __syncthreads();
        if (tid < 128) red[tid] += red[tid + 128] + red[tid + 256];  // 384 -> 128
        __syncthreads();
        for (int st = 64; st > 0; st >>= 1) {
            if (tid < st) red[tid] += red[tid + st];
            __syncthreads();
        }
        if (tid == 0) d_Wsum[o] = red[0];
        return;
    }

    // ---- build path ----
    extern __shared__ float ts[];            // CT*SST floats = 73.76KB
    int c0 = (blk & 63) * CT;
    int b = blk >> 6;

    const float4* src = (const float4*)(feat + ((size_t)(b * CC + c0)) * HW);
    #pragma unroll
    for (int j = 0; j < (CT * HW) / (4 * 384); j++) {
        int i4 = tid + j * 384;
        float4 v = src[i4];
        int c = i4 / (HW / 4);
        int p = (i4 % (HW / 4)) * 4;
        float* d = ts + c * SST + p;
        d[0] = v.x; d[1] = v.y; d[2] = v.z; d[3] = v.w;
    }
    __syncthreads();

    float* const dsts[3] = { d_feat_t, d_lvl, d_lvl + LVLSZ };
    int myc = tid / 48, myw = tid % 48;
    float* col = ts + myc * SST + myw;

    #pragma unroll
    for (int lvl = 0; lvl < 3; lvl++) {
        float* dst = dsts[lvl] + (size_t)b * HW * CC + c0;
        #pragma unroll
        for (int j = 0; j < HW / 384; j++) {
            int p = tid + j * 384;
            float4 v0, v1;
            v0.x = ts[0 * SST + p]; v0.y = ts[1 * SST + p];
            v0.z = ts[2 * SST + p]; v0.w = ts[3 * SST + p];
            v1.x = ts[4 * SST + p]; v1.y = ts[5 * SST + p];
            v1.z = ts[6 * SST + p]; v1.w = ts[7 * SST + p];
            float4* dp = (float4*)(dst + (size_t)p * CC);
            dp[0] = v0; dp[1] = v1;
        }
        if (lvl == 2) break;
        __syncthreads();
        if (lvl == 0) {
            // pw1 -> pw4: in-place ascending passes d=1 then d=2
            for (int h = 0; h < HH - 1; h++)
                col[h * 48] = fmaxf(col[h * 48], col[(h + 1) * 48]);
            for (int h = 0; h < HH - 2; h++)
                col[h * 48] = fmaxf(col[h * 48], col[(h + 2) * 48]);
        } else {
            // pw4 -> pw12: two d=4 passes (pw4->pw8->pw12)
            for (int h = 0; h < HH - 4; h++)
                col[h * 48] = fmaxf(col[h * 48], col[(h + 4) * 48]);
            for (int h = 0; h < HH - 8; h++)
                col[h * 48] = fmaxf(col[h * 48], col[(h + 4) * 48]);
        }
        __syncthreads();
    }
}

// ---------------- K2: ROI pool via range-max lookups + ReLU + BN1 stats --------
__global__ void __launch_bounds__(256) k_roipool(const float* __restrict__ rois) {
    int bn = blockIdx.x;
    int b = bn / NR;
    const float* r = rois + bn * 4;
    int r0 = (int)truncf(r[0] * 0.25f), r1 = (int)truncf(r[1] * 0.25f);
    int r2 = (int)ceilf(r[2] * 0.25f),  r3 = (int)ceilf(r[3] * 0.25f);
    int hs = r2 - r0 + 1, ws = r3 - r1 + 1;
    int lenh = (hs + 1) >> 1;
    int lenw = (ws + 1) >> 1;
    int sh1 = r0 + (hs >> 1);
    int sw1 = r1 + (ws >> 1);

    const float* Lf;
    int pw;
    if (lenh >= 12)     { pw = 12; Lf = d_lvl + (size_t)LVLSZ; }
    else if (lenh >= 4) { pw = 4;  Lf = d_lvl; }
    else                { pw = 1;  Lf = d_feat_t; }
    int nlk = (lenh + pw - 1) / pw;       // 1..3
    const float4* L4 = (const float4*)Lf;

    int tid = threadIdx.x;
    int cq = tid & 127;
    int half = tid >> 7;
    int wstart = half ? sw1 : r1;
    size_t rb = (size_t)(b * HH) * WW;

    const float4 NEG = make_float4(-FLT_MAX, -FLT_MAX, -FLT_MAX, -FLT_MAX);
    float4 m0 = NEG, m1 = NEG;
    int cap = lenh - pw;
    for (int j = 0; j < nlk; j++) {
        int ho = j * pw; if (ho > cap) ho = cap;
        const float4* pA = L4 + (rb + (size_t)(r0  + ho) * WW + wstart) * C4 + cq;
        const float4* pB = L4 + (rb + (size_t)(sh1 + ho) * WW + wstart) * C4 + cq;
        #pragma unroll 2
        for (int w = lenw; w > 0; --w) {
            float4 va = *pA, vb = *pB;
            pA += C4; pB += C4;
            max4(m0, va); max4(m1, vb);
        }
    }

    __shared__ float4 sm0[128], sm1[128];
    __shared__ float rs[128], rq[128];
    if (half == 1) { sm0[cq] = m0; sm1[cq] = m1; }
    __syncthreads();
    if (half == 0) {
        const float4 Z = make_float4(0.f, 0.f, 0.f, 0.f);
        float4 m00 = m0, m10 = m1, m01 = sm0[cq], m11 = sm1[cq];
        max4(m00, Z); max4(m01, Z); max4(m10, Z); max4(m11, Z);
        float4 o0 = make_float4(m00.x, m01.x, m10.x, m11.x);
        float4 o1 = make_float4(m00.y, m01.y, m10.y, m11.y);
        float4 o2 = make_float4(m00.z, m01.z, m10.z, m11.z);
        float4 o3 = make_float4(m00.w, m01.w, m10.w, m11.w);
        float4* out = (float4*)(d_pooled + (size_t)bn * F_IN + cq * 16);
        out[0] = o0; out[1] = o1; out[2] = o2; out[3] = o3;
        float s = (o0.x + o0.y + o0.z + o0.w) + (o1.x + o1.y + o1.z + o1.w)
                + (o2.x + o2.y + o2.z + o2.w) + (o3.x + o3.y + o3.z + o3.w);
        float q = o0.x*o0.x + o0.y*o0.y + o0.z*o0.z + o0.w*o0.w
                + o1.x*o1.x + o1.y*o1.y + o1.z*o1.z + o1.w*o1.w
                + o2.x*o2.x + o2.y*o2.y + o2.z*o2.z + o2.w*o2.w
                + o3.x*o3.x + o3.y*o3.y + o3.z*o3.z + o3.w*o3.w;
        rs[cq] = s; rq[cq] = q;
    }
    __syncthreads();
    for (int st = 64; st > 0; st >>= 1) {
        if (tid < st) { rs[tid] += rs[tid + st]; rq[tid] += rq[tid + st]; }
        __syncthreads();
    }
    if (tid == 0) {
        int n = bn % NR;
        atomicAdd(&d_s1[n], rs[0]);
        atomicAdd(&d_s2[n], rq[0]);
    }
}

// ---------------- K3: GEMM v5 — 12 ROIs x 16 k-slices, 960 blocks ----------------
// 256 threads = 32 o-pairs x 8 q-groups(16k each). No atomics.
__global__ void __launch_bounds__(256) k_gemm() {
    __shared__ float xs[MT][KQ];             // 6KB
    __shared__ float part[8][MT][OO];        // 24KB
    int mb = blockIdx.x;                     // 0..59
    int ks = blockIdx.y;                     // 0..15
    int b = mb / (NR / MT);
    int n0 = (mb % (NR / MT)) * MT;
    int tid = threadIdx.x;

    // load xs: 12 ROIs x 128 k = 384 float4
    const float4* P4 = (const float4*)d_pooled;
    for (int i4 = tid; i4 < MT * (KQ / 4); i4 += 256) {
        int nl = i4 >> 5, k4 = i4 & 31;
        float4 v = P4[((size_t)(b * NR + n0 + nl)) * (F_IN / 4) + ks * (KQ / 4) + k4];
        *(float4*)&xs[nl][k4 * 4] = v;
    }
    __syncthreads();

    int o2 = (tid & 31) * 2;
    int q = tid >> 5;                        // 0..7, covers 16 k (uniform per warp)
    float acc[MT][2] = {};
    const float* Wp = d_W1t + (size_t)(ks * KQ + q * 16) * OO;
    #pragma unroll
    for (int k = 0; k < 16; k += 4) {
        float2 w0 = *(const float2*)&Wp[(k + 0) * OO + o2];
        float2 w1 = *(const float2*)&Wp[(k + 1) * OO + o2];
        float2 w2 = *(const float2*)&Wp[(k + 2) * OO + o2];
        float2 w3 = *(const float2*)&Wp[(k + 3) * OO + o2];
        #pragma unroll
        for (int nl = 0; nl < MT; nl++) {
            float4 x = *(const float4*)&xs[nl][q * 16 + k];
            acc[nl][0] = fmaf(x.x, w0.x, acc[nl][0]);
            acc[nl][1] = fmaf(x.x, w0.y, acc[nl][1]);
            acc[nl][0] = fmaf(x.y, w1.x, acc[nl][0]);
            acc[nl][1] = fmaf(x.y, w1.y, acc[nl][1]);
            acc[nl][0] = fmaf(x.z, w2.x, acc[nl][0]);
            acc[nl][1] = fmaf(x.z, w2.y, acc[nl][1]);
            acc[nl][0] = fmaf(x.w, w3.x, acc[nl][0]);
            acc[nl][1] = fmaf(x.w, w3.y, acc[nl][1]);
        }
    }
    #pragma unroll
    for (int nl = 0; nl < MT; nl++)
        *(float2*)&part[q][nl][o2] = make_float2(acc[nl][0], acc[nl][1]);
    __syncthreads();

    for (int i = tid; i < MT * OO; i += 256) {
        int nl = i >> 6, o = i & 63;
        float g = 0.f;
        #pragma unroll
        for (int qq = 0; qq < 8; qq++) g += part[qq][nl][o];
        d_g16[ks][((size_t)(b * NR + n0 + nl)) * OO + o] = g;
    }
}

// ---------------- K4: finalize BN1 affine + bias + BN2 + write ----------------
__global__ void k_final(const float* __restrict__ gamma1,
                        const float* __restrict__ beta1,
                        const float* __restrict__ bl1,
                        const float* __restrict__ gamma2,
                        const float* __restrict__ beta2,
                        float* __restrict__ out) {
    int n = blockIdx.x;
    int t = threadIdx.x;
    int b = t >> 6, o = t & 63;

    const float inv1 = 1.0f / (BB * F_IN);
    float mean1 = d_s1[n] * inv1;
    float var1 = d_s2[n] * inv1 - mean1 * mean1;
    float a1 = gamma1[n] * rsqrtf(var1 + EPSV);
    float c1 = beta1[n] - a1 * mean1;

    size_t gi = ((size_t)(b * NR + n)) * OO + o;
    float gsum = 0.f;
    #pragma unroll
    for (int ks = 0; ks < KS; ks++) gsum += d_g16[ks][gi];
    float y = a1 * gsum + c1 * d_Wsum[o] + bl1[o];

    __shared__ float rs[256], rq[256];
    rs[t] = y;
    rq[t] = y * y;
    __syncthreads();
    for (int st = 128; st > 0; st >>= 1) {
        if (t < st) { rs[t] += rs[t + st]; rq[t] += rq[t + st]; }
        __syncthreads();
    }
    float mean = rs[0] * (1.0f / 256.0f);
    float var = rq[0] * (1.0f / 256.0f) - mean * mean;
    out[gi] = (y - mean) * rsqrtf(var + EPSV) * gamma2[n] + beta2[n];
}

// ---------------- launch ----------------
extern "C" void kernel_launch(void* const* d_in, const int* in_sizes, int n_in,
                              void* d_out, int out_size) {
    const float* features = (const float*)d_in[0];
    const float* rois     = (const float*)d_in[1];
    const float* gamma1   = (const float*)d_in[2];
    const float* beta1    = (const float*)d_in[3];
    const float* W1       = (const float*)d_in[4];
    const float* bl1      = (const float*)d_in[5];
    const float* gamma2   = (const float*)d_in[6];
    const float* beta2    = (const float*)d_in[7];
    float* out = (float*)d_out;

    static bool attr_done = false;
    const int BUILD_SMEM = CT * SST * 4;     // 73760 B
    if (!attr_done) {
        cudaFuncSetAttribute(k_build, cudaFuncAttributeMaxDynamicSharedMemorySize, BUILD_SMEM);
        attr_done = true;
    }

    k_build<<<(CC / CT) * BB + OO, 384, BUILD_SMEM>>>(features, W1);
    k_roipool<<<BB * NR, 256>>>(rois);
    dim3 ggrid(BB * (NR / MT), KS);
    k_gemm<<<ggrid, 256>>>();
    k_final<<<NR, 256>>>(gamma1, beta1, bl1, gamma2, beta2, out);
}